// round 13
// baseline (speedup 1.0000x reference)
#include <cuda_runtime.h>

// Path signature, depth 3 — fused kernel, TWO t-TEAMS per block.
// path: (32, 128, 48) fp32. Out per batch: [48 | 2304 | 110592] = 112944.
//
// S3[i,j,k] = sum_t w[i][t][j] * v[t][k]
//   v[t][j]    = path[t+1][j] - path[t][j]
//   w[i][t][j] = S2prev[i][j] + (0.5*S1prev[i] + v[t][i]/6) * v[t][j]
//   S2[i][j]  += (S1prev[i] + 0.5*v[t][i]) * v[t][j]
//
// Block (i, b): ONE i-plane, 144 threads = 2 teams of 72. Team h sums its
// t-range (h=0: [0,64); h=1: [64,127) after a register-only warm-up of the
// cheap S2 recurrence). Per-thread tile 4j x 8k = 16 u64 f32x2 accumulators
// (paired along j; w pairs free from 16B shared loads, v dup'd via mov.b64).
// 48 producers per team, pipelined one stage ahead, double-buffered shared,
// one barrier per stage (8 stages). Teams combined through shared memory
// with packed f32x2 adds. Grid (48, 32) = 1536 blocks -> ~36 warps/SM.

#define NB     32
#define LPATH  128
#define C      48
#define NSTEPS 127
#define LVL2   (C * C)
#define STR    (C + LVL2 + C * C * C)   // 112944
#define OFF2   C
#define OFF3   (C + LVL2)
#define TCH    8
#define NST    8        // stages per team (team0: 8x8=64, team1: 7x8+7=63)

typedef unsigned long long u64;

__device__ __forceinline__ void ffma2(u64& d, u64 a, u64 b) {
    asm("fma.rn.f32x2 %0, %1, %2, %0;" : "+l"(d) : "l"(a), "l"(b));
}
__device__ __forceinline__ void fadd2(u64& d, u64 a) {
    asm("add.rn.f32x2 %0, %0, %1;" : "+l"(d) : "l"(a));
}
__device__ __forceinline__ u64 dup_f32(float x) {
    u64 r;
    asm("mov.b64 %0, {%1, %1};" : "=l"(r) : "f"(x));
    return r;
}
__device__ __forceinline__ float2 unpk(u64 a) {
    float2 r;
    asm("mov.b64 {%0, %1}, %2;" : "=f"(r.x), "=f"(r.y) : "l"(a));
    return r;
}

// Shared pool: pipeline views (12KB) and team-combine view (9.2KB) overlap
// in time-disjoint phases.
#define POOL_FLOATS (2 * 2 * TCH * C * 2)   // 6144 floats = 24KB? no: 2 arrays
// v area: [team][buf][t][j] = 2*2*8*48 = 1536 floats; w area same; total 3072.

__device__ __forceinline__ int vidx(int h, int buf, int t, int j) {
    return ((h * 2 + buf) * TCH + t) * C + j;
}
__device__ __forceinline__ int widx(int h, int buf, int t, int j) {
    return 1536 + ((h * 2 + buf) * TCH + t) * C + j;
}

// Phase A: producer (lt < 48) fills v/w for up to 8 steps of stage s.
// tlim is 8 except team1's last stage (7).
__device__ __forceinline__ void phase_a(
    const float* __restrict__ pb, float* __restrict__ pool,
    int h, int buf, int gbase, int tlim, int jj, int i,
    float& p_j, float& p_i, float p0_i, float& S2)
{
#pragma unroll
    for (int t = 0; t < TCH; ++t) {
        if (t < tlim) {
            const float pn_j = pb[(gbase + t + 1) * C + jj];  // coalesced
            const float pn_i = pb[(gbase + t + 1) * C + i];   // broadcast
            const float v_j = pn_j - p_j;
            const float v_i = pn_i - p_i;
            const float s1  = p_i - p0_i;
            pool[vidx(h, buf, t, jj)] = v_j;
            pool[widx(h, buf, t, jj)] =
                fmaf(fmaf(1.0f / 6.0f, v_i, 0.5f * s1), v_j, S2);
            S2 = fmaf(fmaf(0.5f, v_i, s1), v_j, S2);
            p_j = pn_j;
            p_i = pn_i;
        }
    }
}

// Phase B: all threads, up to 8 rank-1 updates of the 4j x 8k tile.
__device__ __forceinline__ void phase_b(
    const float* __restrict__ pool, int h, int buf, int tlim,
    int j0, int k0, u64 (&acc)[2][8])
{
#pragma unroll 2
    for (int t = 0; t < TCH; ++t) {
        if (t < tlim) {
            const ulonglong2 W =
                *(const ulonglong2*)&pool[widx(h, buf, t, j0)];
            const float4 va = *(const float4*)&pool[vidx(h, buf, t, k0)];
            const float4 vb = *(const float4*)&pool[vidx(h, buf, t, k0 + 4)];
            const u64 vp[8] = { dup_f32(va.x), dup_f32(va.y),
                                dup_f32(va.z), dup_f32(va.w),
                                dup_f32(vb.x), dup_f32(vb.y),
                                dup_f32(vb.z), dup_f32(vb.w) };
            const u64 wa[2] = { W.x, W.y };  // (w[j0],w[j0+1]),(w[j0+2],w[j0+3])
#pragma unroll
            for (int jp = 0; jp < 2; ++jp)
#pragma unroll
                for (int kx = 0; kx < 8; ++kx)
                    ffma2(acc[jp][kx], wa[jp], vp[kx]);
        }
    }
}

__global__ __launch_bounds__(144, 8)
void sig_depth3_kernel(const float* __restrict__ path, float* __restrict__ out)
{
    const int i   = blockIdx.x;   // 0..47  (one i-plane per block)
    const int b   = blockIdx.y;   // 0..31
    const int tid = threadIdx.x;  // 0..143

    __shared__ __align__(16) float pool[3072];   // 12KB, dual-purpose

    const float* pb = path + (size_t)b * LPATH * C;

    const int h  = (tid < 72) ? 0 : 1;   // team
    const int lt = tid - 72 * h;         // 0..71

    u64 acc[2][8];
#pragma unroll
    for (int jp = 0; jp < 2; ++jp)
#pragma unroll
        for (int kx = 0; kx < 8; ++kx) acc[jp][kx] = 0ull;

    const int j0 = (lt / 6) * 4;   // 0,4,...,44
    const int k0 = (lt % 6) * 8;   // 0,8,...,40

    const bool prod = (lt < C);
    const int jj = prod ? lt : 0;
    const int tb = h * 64;         // team's first step

    float p_j = 0.0f, p_i = 0.0f, p0_i = 0.0f, S2 = 0.0f;
    if (prod) {
        p_j  = pb[jj];
        p0_i = pb[i];
        p_i  = p0_i;
        if (h == 1) {
            // Warm-up: advance carries through steps 0..63 (register-only).
#pragma unroll 4
            for (int t = 0; t < 64; ++t) {
                const float pn_j = pb[(t + 1) * C + jj];
                const float pn_i = pb[(t + 1) * C + i];
                const float v_j = pn_j - p_j;
                const float v_i = pn_i - p_i;
                const float s1  = p_i - p0_i;
                S2 = fmaf(fmaf(0.5f, v_i, s1), v_j, S2);
                p_j = pn_j;
                p_i = pn_i;
            }
        }
    }

    // Team step counts: team0 64 (8 full stages), team1 63 (last stage = 7).
    const int last_tlim = 8 - h;

    // ---- Pipelined mainloop: A(s+1) before B(s), one barrier per stage ----
    if (prod) phase_a(pb, pool, h, 0, tb, TCH, jj, i, p_j, p_i, p0_i, S2);
    __syncthreads();

#pragma unroll 1
    for (int s = 0; s < NST - 1; ++s) {   // s = 0..6
        const int tlimA = (s + 1 == NST - 1) ? last_tlim : TCH;
        if (prod) phase_a(pb, pool, h, (s + 1) & 1, tb + (s + 1) * TCH, tlimA,
                          jj, i, p_j, p_i, p0_i, S2);
        phase_b(pool, h, s & 1, TCH, j0, k0, acc);
        __syncthreads();
    }
    phase_b(pool, h, (NST - 1) & 1, last_tlim, j0, k0, acc);

    // ---- Team combine through shared memory ----
    // After this barrier all pipeline reads are done; pool is reusable.
    __syncthreads();
    u64* cb = (u64*)pool;                  // 72*16 = 1152 u64 = 9.2KB < 12KB
    if (h == 1) {
#pragma unroll
        for (int n = 0; n < 16; ++n)       // transposed: conflict-free
            cb[n * 72 + lt] = acc[n >> 3][n & 7];
    }
    __syncthreads();
    if (h == 0) {
#pragma unroll
        for (int n = 0; n < 16; ++n)
            fadd2(acc[n >> 3][n & 7], cb[n * 72 + lt]);

        // ---- Epilogue: level 3 (team 0 stores the combined tile) ----
        float* o3 = out + (size_t)b * STR + OFF3 + (size_t)i * LVL2;
#pragma unroll
        for (int jp = 0; jp < 2; ++jp) {
            float lo[8], hi[8];
#pragma unroll
            for (int kx = 0; kx < 8; ++kx) {
                const float2 a = unpk(acc[jp][kx]);
                lo[kx] = a.x; hi[kx] = a.y;
            }
            const int jlo = j0 + 2 * jp, jhi = jlo + 1;
            *(float4*)&o3[jlo * C + k0]     = make_float4(lo[0], lo[1], lo[2], lo[3]);
            *(float4*)&o3[jlo * C + k0 + 4] = make_float4(lo[4], lo[5], lo[6], lo[7]);
            *(float4*)&o3[jhi * C + k0]     = make_float4(hi[0], hi[1], hi[2], hi[3]);
            *(float4*)&o3[jhi * C + k0 + 4] = make_float4(hi[4], hi[5], hi[6], hi[7]);
        }
    } else if (prod) {
        // Team 1 producers hold the FULL-range S2 and path[127].
        float* ob = out + (size_t)b * STR;
        ob[OFF2 + i * C + jj] = S2;        // level 2, row i
        if (i == 0) {
            ob[jj] = p_j - pb[jj];         // level 1
        }
    }
}

extern "C" void kernel_launch(void* const* d_in, const int* in_sizes, int n_in,
                              void* d_out, int out_size)
{
    (void)in_sizes; (void)n_in; (void)out_size;
    const float* path = (const float*)d_in[0];
    float* out = (float*)d_out;
    dim3 grid(C, NB);       // (i, batch) = (48, 32) -> 1536 blocks
    dim3 block(144);
    sig_depth3_kernel<<<grid, block>>>(path, out);
}

// round 14
// speedup vs baseline: 1.3343x; 1.3343x over previous
#include <cuda_runtime.h>

// Path signature, depth 3 — fused kernel, ONE i-plane per block.
// path: (32, 128, 48) fp32. Out per batch: [48 | 2304 | 110592] = 112944.
//
// S3[i,j,k] = sum_t w[i][t][j] * v[t][k]
//   v[t][j]    = path[t+1][j] - path[t][j]
//   w[i][t][j] = S2prev[i][j] + (0.5*S1prev[i] + v[t][i]/6) * v[t][j]
//   S2[i][j]  += (S1prev[i] + 0.5*v[t][i]) * v[t][j]
//
// Block (i, b): one 48x48 (j,k) tile. 96 threads = 12(j-grp) x 8(k-grp);
// per-thread 4j x 6k = 12 u64 f32x2 accumulators (paired along j: w pairs
// come free from one 16B shared load; v dup'd via mov.b64).
// Producers = threads 0..47; thread jj's w-recurrence already computes v_jj,
// so v costs nothing extra. 1536 blocks x 48 producers = exactly the 73728
// required w-rows: ZERO duplicated serial work. Producers pipelined one
// chunk ahead; T=16 double-buffered stages, one barrier per stage (8 total).
// 1536 blocks x 3 warps -> ~31 resident warps/SM.

#define NB     32
#define LPATH  128
#define C      48
#define NSTEPS 127
#define LVL2   (C * C)
#define STR    (C + LVL2 + C * C * C)   // 112944
#define OFF2   C
#define OFF3   (C + LVL2)
#define TCH    16
#define NFULL  7                        // 7 full chunks of 16 = 112
#define TAILT  (NSTEPS - NFULL * TCH)   // 15

typedef unsigned long long u64;

__device__ __forceinline__ void ffma2(u64& d, u64 a, u64 b) {
    asm("fma.rn.f32x2 %0, %1, %2, %0;" : "+l"(d) : "l"(a), "l"(b));
}
__device__ __forceinline__ u64 dup_f32(float x) {
    u64 r;
    asm("mov.b64 %0, {%1, %1};" : "=l"(r) : "f"(x));
    return r;
}
__device__ __forceinline__ float2 unpk(u64 a) {
    float2 r;
    asm("mov.b64 {%0, %1}, %2;" : "=f"(r.x), "=f"(r.y) : "l"(a));
    return r;
}

// Phase A: producer thread jj (< 48) fills v and w for T steps of a chunk.
template<int T>
__device__ __forceinline__ void phase_a(
    const float* __restrict__ pb, int base_t, int buf, int i, int jj,
    float& p_j, float& p_i, float p0_i, float& S2,
    float (*sh_v)[TCH][C], float (*sh_w)[TCH][C])
{
#pragma unroll
    for (int t = 0; t < T; ++t) {
        const float pn_j = pb[(base_t + t + 1) * C + jj];  // coalesced
        const float pn_i = pb[(base_t + t + 1) * C + i];   // broadcast
        const float v_j = pn_j - p_j;
        const float v_i = pn_i - p_i;
        const float s1  = p_i - p0_i;
        sh_v[buf][t][jj] = v_j;                            // v is free here
        sh_w[buf][t][jj] = fmaf(fmaf(1.0f / 6.0f, v_i, 0.5f * s1), v_j, S2);
        S2 = fmaf(fmaf(0.5f, v_i, s1), v_j, S2);
        p_j = pn_j;
        p_i = pn_i;
    }
}

// Phase B: all 96 threads, T rank-1 updates of the 4j x 6k tile.
template<int T>
__device__ __forceinline__ void phase_b(
    int buf, int j0, int k0, u64 (&acc)[2][6],
    float (*sh_v)[TCH][C], float (*sh_w)[TCH][C])
{
#pragma unroll 2
    for (int t = 0; t < T; ++t) {
        const ulonglong2 W = *(const ulonglong2*)&sh_w[buf][t][j0]; // 16B
        const float2 vab = *(const float2*)&sh_v[buf][t][k0];       // 8B
        const float2 vcd = *(const float2*)&sh_v[buf][t][k0 + 2];
        const float2 vef = *(const float2*)&sh_v[buf][t][k0 + 4];
        const u64 vp[6] = { dup_f32(vab.x), dup_f32(vab.y),
                            dup_f32(vcd.x), dup_f32(vcd.y),
                            dup_f32(vef.x), dup_f32(vef.y) };
        const u64 wa[2] = { W.x, W.y };   // j-pairs (j0,j0+1),(j0+2,j0+3)
#pragma unroll
        for (int jp = 0; jp < 2; ++jp)
#pragma unroll
            for (int kx = 0; kx < 6; ++kx)
                ffma2(acc[jp][kx], wa[jp], vp[kx]);
    }
}

__global__ __launch_bounds__(96, 10)
void sig_depth3_kernel(const float* __restrict__ path, float* __restrict__ out)
{
    const int i   = blockIdx.x;   // 0..47  (one i-plane per block)
    const int b   = blockIdx.y;   // 0..31
    const int tid = threadIdx.x;  // 0..95

    __shared__ __align__(16) float sh_v[2][TCH][C];   // 6KB
    __shared__ __align__(16) float sh_w[2][TCH][C];   // 6KB

    const float* pb = path + (size_t)b * LPATH * C;

    u64 acc[2][6];
#pragma unroll
    for (int jp = 0; jp < 2; ++jp)
#pragma unroll
        for (int kx = 0; kx < 6; ++kx) acc[jp][kx] = 0ull;

    const int j0 = (tid / 8) * 4;   // 0,4,...,44  (12 j-groups)
    const int k0 = (tid % 8) * 6;   // 0,6,...,42  (8 k-groups, even)

    const bool prod = (tid < C);
    const int jj = prod ? tid : 0;

    float p_j = 0.0f, p_i = 0.0f, p0_i = 0.0f, S2 = 0.0f;
    if (prod) {
        p_j  = pb[jj];
        p0_i = pb[i];
        p_i  = p0_i;
    }

    // ---- Pipelined mainloop: A(s+1) before B(s), one barrier per stage ----
    if (prod) phase_a<TCH>(pb, 0, 0, i, jj, p_j, p_i, p0_i, S2, sh_v, sh_w);
    __syncthreads();

#pragma unroll 1
    for (int s = 0; s < NFULL - 1; ++s) {   // s = 0..5
        if (prod) phase_a<TCH>(pb, (s + 1) * TCH, (s + 1) & 1, i, jj,
                               p_j, p_i, p0_i, S2, sh_v, sh_w);
        phase_b<TCH>(s & 1, j0, k0, acc, sh_v, sh_w);
        __syncthreads();
    }
    // Stage 6: produce tail (15 steps) into buf 1, consume chunk 6 (buf 0).
    if (prod) phase_a<TAILT>(pb, NFULL * TCH, NFULL & 1, i, jj,
                             p_j, p_i, p0_i, S2, sh_v, sh_w);
    phase_b<TCH>((NFULL - 1) & 1, j0, k0, acc, sh_v, sh_w);
    __syncthreads();
    phase_b<TAILT>(NFULL & 1, j0, k0, acc, sh_v, sh_w);

    // ---- Epilogue ----
    float* ob = out + (size_t)b * STR;
    float* o3 = ob + OFF3 + (size_t)i * LVL2;
#pragma unroll
    for (int jp = 0; jp < 2; ++jp) {
        float lo[6], hi[6];
#pragma unroll
        for (int kx = 0; kx < 6; ++kx) {
            const float2 a = unpk(acc[jp][kx]);
            lo[kx] = a.x; hi[kx] = a.y;
        }
        const int jlo = j0 + 2 * jp, jhi = jlo + 1;
#pragma unroll
        for (int kp = 0; kp < 3; ++kp) {   // float2 stores, 8B aligned
            *(float2*)&o3[jlo * C + k0 + 2 * kp] = make_float2(lo[2*kp], lo[2*kp+1]);
            *(float2*)&o3[jhi * C + k0 + 2 * kp] = make_float2(hi[2*kp], hi[2*kp+1]);
        }
    }

    if (prod) {
        ob[OFF2 + i * C + jj] = S2;        // level 2, row i
        if (i == 0) {
            // p_j now holds path[b][127][jj]
            ob[jj] = p_j - pb[jj];         // level 1
        }
    }
}

extern "C" void kernel_launch(void* const* d_in, const int* in_sizes, int n_in,
                              void* d_out, int out_size)
{
    (void)in_sizes; (void)n_in; (void)out_size;
    const float* path = (const float*)d_in[0];
    float* out = (float*)d_out;
    dim3 grid(C, NB);       // (i, batch) = (48, 32) -> 1536 blocks
    dim3 block(96);
    sig_depth3_kernel<<<grid, block>>>(path, out);
}

// round 15
// speedup vs baseline: 1.9923x; 1.4932x over previous
#include <cuda_runtime.h>

// Path signature, depth 3 — R6 architecture (best: 37.4us) + path staged in
// shared memory. path: (32, 128, 48) fp32. Out: [48 | 2304 | 110592]/batch.
//
// S3[i,j,k] = sum_t w[i][t][j] * v[t][k]
//   v[t][j]    = path[t+1][j] - path[t][j]
//   w[i][t][j] = S2prev[i][j] + (0.5*S1prev[i] + v[t][i]/6) * v[t][j]
//   S2[i][j]  += (S1prev[i] + 0.5*v[t][i]) * v[t][j]
//
// Block (bx,b): two i-planes, two 48x48 (j,k) reg tiles, 144 threads,
// 4x4 per thread per plane, packed fma.rn.f32x2 along j (w pairs free from
// 16B shared loads; v dup'd via mov.b64). Producers (threads 0..95) are
// pipelined one chunk ahead; double-buffered v/w, one barrier per stage.
// NEW: the 24KB path block is copied to shared once, so phase A's loads are
// LDS (29cyc) instead of L2 LDG (234cyc), shortening the produce chain that
// gates every stage barrier.

#define NB     32
#define LPATH  128
#define C      48
#define NSTEPS (LPATH - 1)          // 127
#define LVL2   (C * C)
#define STR    (C + LVL2 + C * C * C)   // 112944
#define OFF2   C
#define OFF3   (C + LVL2)
#define TCH    8
#define NFULL  15
#define TAILT  (NSTEPS - NFULL * TCH)   // 7

typedef unsigned long long u64;

__device__ __forceinline__ void ffma2(u64& d, u64 a, u64 b) {
    asm("fma.rn.f32x2 %0, %1, %2, %0;" : "+l"(d) : "l"(a), "l"(b));
}
__device__ __forceinline__ u64 dup_f32(float x) {
    u64 r;
    asm("mov.b64 %0, {%1, %1};" : "=l"(r) : "f"(x));
    return r;
}
__device__ __forceinline__ float2 unpk(u64 a) {
    float2 r;
    asm("mov.b64 {%0, %1}, %2;" : "=f"(r.x), "=f"(r.y) : "l"(a));
    return r;
}

// Phase A: producer thread (tid < 96) computes v/w for T steps of one chunk,
// reading the path from SHARED memory.
template<int T>
__device__ __forceinline__ void phase_a(
    const float* __restrict__ sp, int base_t, int buf, int i_r, int r, int jj,
    float& p_j, float& p_i, float p0_i, float& S2,
    float (*sh_v)[TCH][C], float (*sh_w)[2][TCH][C])
{
#pragma unroll
    for (int t = 0; t < T; ++t) {
        const float pn_j = sp[(base_t + t + 1) * C + jj];  // LDS, stride-1
        const float pn_i = sp[(base_t + t + 1) * C + i_r]; // LDS broadcast
        const float v_j = pn_j - p_j;
        const float v_i = pn_i - p_i;
        const float s1  = p_i - p0_i;
        if (r == 0) sh_v[buf][t][jj] = v_j;
        sh_w[buf][r][t][jj] = fmaf(fmaf(1.0f / 6.0f, v_i, 0.5f * s1), v_j, S2);
        S2 = fmaf(fmaf(0.5f, v_i, s1), v_j, S2);
        p_j = pn_j;
        p_i = pn_i;
    }
}

// Phase B: all threads, T rank-1 updates of both 4x4 tiles (f32x2 packed).
template<int T>
__device__ __forceinline__ void phase_b(
    int buf, int j0, int k0, u64 (&acc0)[2][4], u64 (&acc1)[2][4],
    float (*sh_v)[TCH][C], float (*sh_w)[2][TCH][C])
{
#pragma unroll 4
    for (int t = 0; t < T; ++t) {
        const ulonglong2 w0 = *(const ulonglong2*)&sh_w[buf][0][t][j0];
        const ulonglong2 w1 = *(const ulonglong2*)&sh_w[buf][1][t][j0];
        const float4     vv = *(const float4*)&sh_v[buf][t][k0];
        const u64 vp[4] = { dup_f32(vv.x), dup_f32(vv.y),
                            dup_f32(vv.z), dup_f32(vv.w) };
        const u64 wa[2] = { w0.x, w0.y };
        const u64 wb[2] = { w1.x, w1.y };
#pragma unroll
        for (int jp = 0; jp < 2; ++jp)
#pragma unroll
            for (int kx = 0; kx < 4; ++kx) {
                ffma2(acc0[jp][kx], wa[jp], vp[kx]);
                ffma2(acc1[jp][kx], wb[jp], vp[kx]);
            }
    }
}

__global__ __launch_bounds__(144, 6)
void sig_depth3_kernel(const float* __restrict__ path, float* __restrict__ out)
{
    const int bx  = blockIdx.x;   // 0..23 -> i0 = 2bx, i1 = 2bx+1
    const int b   = blockIdx.y;   // 0..31
    const int tid = threadIdx.x;  // 0..143

    __shared__ __align__(16) float sp[LPATH * C];        // 24KB path block
    __shared__ __align__(16) float sh_v[2][TCH][C];      // 3KB
    __shared__ __align__(16) float sh_w[2][2][TCH][C];   // 6KB

    const float* pb = path + (size_t)b * LPATH * C;

    // ---- Stage the path block into shared (coalesced float4) ----
    {
        const float4* src = (const float4*)pb;
        float4* dst = (float4*)sp;
#pragma unroll
        for (int idx = tid; idx < (LPATH * C) / 4; idx += 144)
            dst[idx] = src[idx];
    }

    u64 acc0[2][4], acc1[2][4];
#pragma unroll
    for (int jp = 0; jp < 2; ++jp)
#pragma unroll
        for (int kx = 0; kx < 4; ++kx) { acc0[jp][kx] = 0ull; acc1[jp][kx] = 0ull; }

    const int j0 = (tid / 12) * 4;
    const int k0 = (tid % 12) * 4;

    const bool prod = (tid < 2 * C);
    const int r   = (tid < C) ? 0 : 1;
    const int jj  = prod ? (tid - r * C) : 0;
    const int i_r = 2 * bx + r;

    __syncthreads();   // path staged before any phase-A read

    float p_j = 0.0f, p_i = 0.0f, p0_i = 0.0f, S2 = 0.0f;
    if (prod) {
        p_j  = sp[jj];
        p0_i = sp[i_r];
        p_i  = p0_i;
    }

    // ---- Pipelined mainloop: A(s+1) before B(s), one barrier per stage ----
    if (prod) phase_a<TCH>(sp, 0, 0, i_r, r, jj, p_j, p_i, p0_i, S2,
                           sh_v, sh_w);
    __syncthreads();

#pragma unroll 1
    for (int s = 0; s < NFULL - 1; ++s) {     // s = 0..13
        if (prod) phase_a<TCH>(sp, (s + 1) * TCH, (s + 1) & 1, i_r, r, jj,
                               p_j, p_i, p0_i, S2, sh_v, sh_w);
        phase_b<TCH>(s & 1, j0, k0, acc0, acc1, sh_v, sh_w);
        __syncthreads();
    }
    // s = 14: produce tail chunk (7 steps), consume chunk 14
    if (prod) phase_a<TAILT>(sp, NFULL * TCH, NFULL & 1, i_r, r, jj,
                             p_j, p_i, p0_i, S2, sh_v, sh_w);
    phase_b<TCH>((NFULL - 1) & 1, j0, k0, acc0, acc1, sh_v, sh_w);
    __syncthreads();
    phase_b<TAILT>(NFULL & 1, j0, k0, acc0, acc1, sh_v, sh_w);

    // ---- Epilogue ----
    float* ob = out + (size_t)b * STR;

    float* o30 = ob + OFF3 + (size_t)(2 * bx)     * LVL2;
    float* o31 = ob + OFF3 + (size_t)(2 * bx + 1) * LVL2;
#pragma unroll
    for (int jp = 0; jp < 2; ++jp) {
        float2 a00 = unpk(acc0[jp][0]), a01 = unpk(acc0[jp][1]);
        float2 a02 = unpk(acc0[jp][2]), a03 = unpk(acc0[jp][3]);
        float2 b00 = unpk(acc1[jp][0]), b01 = unpk(acc1[jp][1]);
        float2 b02 = unpk(acc1[jp][2]), b03 = unpk(acc1[jp][3]);
        const int jlo = j0 + 2 * jp, jhi = jlo + 1;
        *(float4*)&o30[jlo * C + k0] = make_float4(a00.x, a01.x, a02.x, a03.x);
        *(float4*)&o30[jhi * C + k0] = make_float4(a00.y, a01.y, a02.y, a03.y);
        *(float4*)&o31[jlo * C + k0] = make_float4(b00.x, b01.x, b02.x, b03.x);
        *(float4*)&o31[jhi * C + k0] = make_float4(b00.y, b01.y, b02.y, b03.y);
    }

    if (prod) {
        ob[OFF2 + i_r * C + jj] = S2;            // level 2, rows i0/i1
        if (bx == 0 && r == 0) {
            // p_j now holds path[b][127][jj]
            ob[jj] = p_j - sp[jj];               // level 1
        }
    }
}

extern "C" void kernel_launch(void* const* d_in, const int* in_sizes, int n_in,
                              void* d_out, int out_size)
{
    (void)in_sizes; (void)n_in; (void)out_size;
    const float* path = (const float*)d_in[0];
    float* out = (float*)d_out;
    dim3 grid(C / 2, NB);   // (i-pairs, batch) = (24, 32)
    dim3 block(144);
    sig_depth3_kernel<<<grid, block>>>(path, out);
}

// round 16
// speedup vs baseline: 2.1097x; 1.0589x over previous
#include <cuda_runtime.h>

// Path signature, depth 3 — R15 architecture (path staged in smem) with
// TCH=16: half the stages/barriers. path: (32,128,48) fp32.
// Out per batch: [48 | 2304 | 110592] = 112944.
//
// S3[i,j,k] = sum_t w[i][t][j] * v[t][k]
//   v[t][j]    = path[t+1][j] - path[t][j]
//   w[i][t][j] = S2prev[i][j] + (0.5*S1prev[i] + v[t][i]/6) * v[t][j]
//   S2[i][j]  += (S1prev[i] + 0.5*v[t][i]) * v[t][j]
//
// Block (bx,b): two i-planes, two 48x48 (j,k) reg tiles, 144 threads,
// 4x4 per thread per plane, packed fma.rn.f32x2 along j (w pairs free from
// 16B shared loads; v dup'd via mov.b64). Producers (threads 0..95) are
// pipelined one chunk ahead; double-buffered v/w, one barrier per stage
// (8 stages of 16 steps; tail 15). 24KB path block staged in shared so the
// producer chain is LDS-fed (29cyc) rather than L2 (234cyc).

#define NB     32
#define LPATH  128
#define C      48
#define NSTEPS (LPATH - 1)          // 127
#define LVL2   (C * C)
#define STR    (C + LVL2 + C * C * C)   // 112944
#define OFF2   C
#define OFF3   (C + LVL2)
#define TCH    16
#define NFULL  7                        // 7 full chunks of 16 = 112
#define TAILT  (NSTEPS - NFULL * TCH)   // 15

typedef unsigned long long u64;

__device__ __forceinline__ void ffma2(u64& d, u64 a, u64 b) {
    asm("fma.rn.f32x2 %0, %1, %2, %0;" : "+l"(d) : "l"(a), "l"(b));
}
__device__ __forceinline__ u64 dup_f32(float x) {
    u64 r;
    asm("mov.b64 %0, {%1, %1};" : "=l"(r) : "f"(x));
    return r;
}
__device__ __forceinline__ float2 unpk(u64 a) {
    float2 r;
    asm("mov.b64 {%0, %1}, %2;" : "=f"(r.x), "=f"(r.y) : "l"(a));
    return r;
}

// Phase A: producer thread (tid < 96) computes v/w for T steps of one chunk,
// reading the path from SHARED memory.
template<int T>
__device__ __forceinline__ void phase_a(
    const float* __restrict__ sp, int base_t, int buf, int i_r, int r, int jj,
    float& p_j, float& p_i, float p0_i, float& S2,
    float (*sh_v)[TCH][C], float (*sh_w)[2][TCH][C])
{
#pragma unroll
    for (int t = 0; t < T; ++t) {
        const float pn_j = sp[(base_t + t + 1) * C + jj];  // LDS, stride-1
        const float pn_i = sp[(base_t + t + 1) * C + i_r]; // LDS broadcast
        const float v_j = pn_j - p_j;
        const float v_i = pn_i - p_i;
        const float s1  = p_i - p0_i;
        if (r == 0) sh_v[buf][t][jj] = v_j;
        sh_w[buf][r][t][jj] = fmaf(fmaf(1.0f / 6.0f, v_i, 0.5f * s1), v_j, S2);
        S2 = fmaf(fmaf(0.5f, v_i, s1), v_j, S2);
        p_j = pn_j;
        p_i = pn_i;
    }
}

// Phase B: all threads, T rank-1 updates of both 4x4 tiles (f32x2 packed).
template<int T>
__device__ __forceinline__ void phase_b(
    int buf, int j0, int k0, u64 (&acc0)[2][4], u64 (&acc1)[2][4],
    float (*sh_v)[TCH][C], float (*sh_w)[2][TCH][C])
{
#pragma unroll 4
    for (int t = 0; t < T; ++t) {
        const ulonglong2 w0 = *(const ulonglong2*)&sh_w[buf][0][t][j0];
        const ulonglong2 w1 = *(const ulonglong2*)&sh_w[buf][1][t][j0];
        const float4     vv = *(const float4*)&sh_v[buf][t][k0];
        const u64 vp[4] = { dup_f32(vv.x), dup_f32(vv.y),
                            dup_f32(vv.z), dup_f32(vv.w) };
        const u64 wa[2] = { w0.x, w0.y };
        const u64 wb[2] = { w1.x, w1.y };
#pragma unroll
        for (int jp = 0; jp < 2; ++jp)
#pragma unroll
            for (int kx = 0; kx < 4; ++kx) {
                ffma2(acc0[jp][kx], wa[jp], vp[kx]);
                ffma2(acc1[jp][kx], wb[jp], vp[kx]);
            }
    }
}

__global__ __launch_bounds__(144, 5)
void sig_depth3_kernel(const float* __restrict__ path, float* __restrict__ out)
{
    const int bx  = blockIdx.x;   // 0..23 -> i0 = 2bx, i1 = 2bx+1
    const int b   = blockIdx.y;   // 0..31
    const int tid = threadIdx.x;  // 0..143

    __shared__ __align__(16) float sp[LPATH * C];        // 24KB path block
    __shared__ __align__(16) float sh_v[2][TCH][C];      // 6KB
    __shared__ __align__(16) float sh_w[2][2][TCH][C];   // 12KB

    const float* pb = path + (size_t)b * LPATH * C;

    // ---- Stage the path block into shared (coalesced float4) ----
    {
        const float4* src = (const float4*)pb;
        float4* dst = (float4*)sp;
#pragma unroll
        for (int idx = tid; idx < (LPATH * C) / 4; idx += 144)
            dst[idx] = src[idx];
    }

    u64 acc0[2][4], acc1[2][4];
#pragma unroll
    for (int jp = 0; jp < 2; ++jp)
#pragma unroll
        for (int kx = 0; kx < 4; ++kx) { acc0[jp][kx] = 0ull; acc1[jp][kx] = 0ull; }

    const int j0 = (tid / 12) * 4;
    const int k0 = (tid % 12) * 4;

    const bool prod = (tid < 2 * C);
    const int r   = (tid < C) ? 0 : 1;
    const int jj  = prod ? (tid - r * C) : 0;
    const int i_r = 2 * bx + r;

    __syncthreads();   // path staged before any phase-A read

    float p_j = 0.0f, p_i = 0.0f, p0_i = 0.0f, S2 = 0.0f;
    if (prod) {
        p_j  = sp[jj];
        p0_i = sp[i_r];
        p_i  = p0_i;
    }

    // ---- Pipelined mainloop: A(s+1) before B(s), one barrier per stage ----
    if (prod) phase_a<TCH>(sp, 0, 0, i_r, r, jj, p_j, p_i, p0_i, S2,
                           sh_v, sh_w);
    __syncthreads();

#pragma unroll 1
    for (int s = 0; s < NFULL - 1; ++s) {     // s = 0..5
        if (prod) phase_a<TCH>(sp, (s + 1) * TCH, (s + 1) & 1, i_r, r, jj,
                               p_j, p_i, p0_i, S2, sh_v, sh_w);
        phase_b<TCH>(s & 1, j0, k0, acc0, acc1, sh_v, sh_w);
        __syncthreads();
    }
    // s = 6: produce tail chunk (15 steps) into buf 1, consume chunk 6.
    if (prod) phase_a<TAILT>(sp, NFULL * TCH, NFULL & 1, i_r, r, jj,
                             p_j, p_i, p0_i, S2, sh_v, sh_w);
    phase_b<TCH>((NFULL - 1) & 1, j0, k0, acc0, acc1, sh_v, sh_w);
    __syncthreads();
    phase_b<TAILT>(NFULL & 1, j0, k0, acc0, acc1, sh_v, sh_w);

    // ---- Epilogue ----
    float* ob = out + (size_t)b * STR;

    float* o30 = ob + OFF3 + (size_t)(2 * bx)     * LVL2;
    float* o31 = ob + OFF3 + (size_t)(2 * bx + 1) * LVL2;
#pragma unroll
    for (int jp = 0; jp < 2; ++jp) {
        float2 a00 = unpk(acc0[jp][0]), a01 = unpk(acc0[jp][1]);
        float2 a02 = unpk(acc0[jp][2]), a03 = unpk(acc0[jp][3]);
        float2 b00 = unpk(acc1[jp][0]), b01 = unpk(acc1[jp][1]);
        float2 b02 = unpk(acc1[jp][2]), b03 = unpk(acc1[jp][3]);
        const int jlo = j0 + 2 * jp, jhi = jlo + 1;
        *(float4*)&o30[jlo * C + k0] = make_float4(a00.x, a01.x, a02.x, a03.x);
        *(float4*)&o30[jhi * C + k0] = make_float4(a00.y, a01.y, a02.y, a03.y);
        *(float4*)&o31[jlo * C + k0] = make_float4(b00.x, b01.x, b02.x, b03.x);
        *(float4*)&o31[jhi * C + k0] = make_float4(b00.y, b01.y, b02.y, b03.y);
    }

    if (prod) {
        ob[OFF2 + i_r * C + jj] = S2;            // level 2, rows i0/i1
        if (bx == 0 && r == 0) {
            // p_j now holds path[b][127][jj]
            ob[jj] = p_j - sp[jj];               // level 1
        }
    }
}

extern "C" void kernel_launch(void* const* d_in, const int* in_sizes, int n_in,
                              void* d_out, int out_size)
{
    (void)in_sizes; (void)n_in; (void)out_size;
    const float* path = (const float*)d_in[0];
    float* out = (float*)d_out;
    dim3 grid(C / 2, NB);   // (i-pairs, batch) = (24, 32)
    dim3 block(144);
    sig_depth3_kernel<<<grid, block>>>(path, out);
}